// round 10
// baseline (speedup 1.0000x reference)
#include <cuda_runtime.h>
#include <cuda_bf16.h>
#include <math.h>

// ---------------------------------------------------------------------------
// SearchNet: cosine similarity top-k
//   query [512] f32, database [N,512] f32 (N=500000), top_num=100
//   out: [values(K) | indices-as-float(K)] where K = out_size/2
//
// Pipeline (2 kernels, no grid barriers):
//   sims   : dot(q_raw,d)/|d| -> sortable keys. Lane 0 ALSO appends
//            (key,idx) to a global candidate list when key > f2key(T0)
//            (T0=0.105; ~0.9% of rows for N(0,1/512) sims -> ~4400 appends,
//            negligible atomic traffic). Top-K threshold (~0.156) >> T0.
//   select : ONE block, 1024 threads:
//              fast path (K <= ncand <= 4864): stage candidates in smem,
//                2048-bin hist of candidates, block scan -> exact bin
//                threshold, compact survivors (~100-400), exact m^2 rank,
//                write top-K scaled by 1/|q|, reset counter.
//              fallback (any other data): full hist + collect over g_keys
//                inside this block — slow but correct for arbitrary input.
// ---------------------------------------------------------------------------

#define D 512
#define MAXN (1 << 20)        // >= 500000
#define CAND_CAP 16384
#define SCK_CAP 4864          // staged candidates (38.9KB of smem as u64)
#define LST_CAP 1024          // compacted above-threshold list (reuses hist)
#define T0 0.105f

__device__ unsigned int g_keys[MAXN];
__device__ unsigned int g_ncand;                    // zero at load; reset by select
__device__ unsigned int g_cand_key[CAND_CAP];
__device__ unsigned int g_cand_idx[CAND_CAP];

// float -> order-preserving uint
__device__ __forceinline__ unsigned int f2key(float f) {
    unsigned int u = __float_as_uint(f);
    return (u & 0x80000000u) ? ~u : (u | 0x80000000u);
}
__device__ __forceinline__ float key2f(unsigned int k) {
    unsigned int u = (k & 0x80000000u) ? (k ^ 0x80000000u) : ~k;
    return __uint_as_float(u);
}

// ---------------- sims: dot(q,d)/|d|, 2 rows per warp + candidate append ---
__global__ __launch_bounds__(256) void sims_kernel(const float* __restrict__ db,
                                                   const float* __restrict__ q,
                                                   int N) {
    int warp = (blockIdx.x * blockDim.x + threadIdx.x) >> 5;
    int lane = threadIdx.x & 31;
    int r0 = warp * 2;
    if (r0 >= N) return;
    bool has1 = (r0 + 1) < N;

    const float4* q4 = (const float4*)q;
    float4 q0 = __ldg(&q4[lane]);
    float4 q1 = __ldg(&q4[lane + 32]);
    float4 q2 = __ldg(&q4[lane + 64]);
    float4 q3 = __ldg(&q4[lane + 96]);

    const float4* rowA = (const float4*)(db + (size_t)r0 * D);
    const float4* rowB = (const float4*)(db + (size_t)(r0 + (has1 ? 1 : 0)) * D);

    // front-batch 8 independent streaming DRAM loads (touch-once data)
    float4 a0 = __ldcs(&rowA[lane]);
    float4 a1 = __ldcs(&rowA[lane + 32]);
    float4 a2 = __ldcs(&rowA[lane + 64]);
    float4 a3 = __ldcs(&rowA[lane + 96]);
    float4 b0 = __ldcs(&rowB[lane]);
    float4 b1 = __ldcs(&rowB[lane + 32]);
    float4 b2 = __ldcs(&rowB[lane + 64]);
    float4 b3 = __ldcs(&rowB[lane + 96]);

    float dotA = a0.x*q0.x + a0.y*q0.y + a0.z*q0.z + a0.w*q0.w
               + a1.x*q1.x + a1.y*q1.y + a1.z*q1.z + a1.w*q1.w
               + a2.x*q2.x + a2.y*q2.y + a2.z*q2.z + a2.w*q2.w
               + a3.x*q3.x + a3.y*q3.y + a3.z*q3.z + a3.w*q3.w;
    float n2A  = a0.x*a0.x + a0.y*a0.y + a0.z*a0.z + a0.w*a0.w
               + a1.x*a1.x + a1.y*a1.y + a1.z*a1.z + a1.w*a1.w
               + a2.x*a2.x + a2.y*a2.y + a2.z*a2.z + a2.w*a2.w
               + a3.x*a3.x + a3.y*a3.y + a3.z*a3.z + a3.w*a3.w;
    float dotB = b0.x*q0.x + b0.y*q0.y + b0.z*q0.z + b0.w*q0.w
               + b1.x*q1.x + b1.y*q1.y + b1.z*q1.z + b1.w*q1.w
               + b2.x*q2.x + b2.y*q2.y + b2.z*q2.z + b2.w*q2.w
               + b3.x*q3.x + b3.y*q3.y + b3.z*q3.z + b3.w*q3.w;
    float n2B  = b0.x*b0.x + b0.y*b0.y + b0.z*b0.z + b0.w*b0.w
               + b1.x*b1.x + b1.y*b1.y + b1.z*b1.z + b1.w*b1.w
               + b2.x*b2.x + b2.y*b2.y + b2.z*b2.z + b2.w*b2.w
               + b3.x*b3.x + b3.y*b3.y + b3.z*b3.z + b3.w*b3.w;

#pragma unroll
    for (int off = 16; off; off >>= 1) {
        dotA += __shfl_down_sync(0xFFFFFFFFu, dotA, off);
        n2A  += __shfl_down_sync(0xFFFFFFFFu, n2A, off);
        dotB += __shfl_down_sync(0xFFFFFFFFu, dotB, off);
        n2B  += __shfl_down_sync(0xFFFFFFFFu, n2B, off);
    }
    if (lane == 0) {
        unsigned int t0key = f2key(T0);   // compile-time constant
        unsigned int kA = f2key(dotA / fmaxf(sqrtf(n2A), 1e-8f));
        g_keys[r0] = kA;
        if (kA > t0key) {
            unsigned int p = atomicAdd(&g_ncand, 1u);
            if (p < CAND_CAP) { g_cand_key[p] = kA; g_cand_idx[p] = (unsigned int)r0; }
        }
        if (has1) {
            unsigned int kB = f2key(dotB / fmaxf(sqrtf(n2B), 1e-8f));
            g_keys[r0 + 1] = kB;
            if (kB > t0key) {
                unsigned int p = atomicAdd(&g_ncand, 1u);
                if (p < CAND_CAP) { g_cand_key[p] = kB; g_cand_idx[p] = (unsigned int)(r0 + 1); }
            }
        }
    }
}

// ---------------- select: single block, hist-of-candidates + exact rank ----
__global__ __launch_bounds__(1024) void select_kernel(
        const float* __restrict__ q, float* __restrict__ out, int N, int K) {
    __shared__ unsigned long long sck[SCK_CAP];  // 38.9KB staged candidates
    __shared__ unsigned int hist[2048];          // 8KB; reused as u64 list later
    __shared__ unsigned int wsum2[32];
    __shared__ unsigned int s_sel, scnt, fcnt;
    __shared__ float qs[32];
    __shared__ float qinv;

    int t = threadIdx.x;
    int lane = t & 31;
    int w = t >> 5;

    unsigned int n = g_ncand;                    // raw append count
    bool fast = (n >= (unsigned int)K && n <= SCK_CAP);

    for (int i = t; i < 2048; i += 1024) hist[i] = 0;
    if (t == 0) { scnt = 0; fcnt = 0; }
    __syncthreads();

    // ---- phase 1: histogram (candidates only, or full keys on fallback) ---
    if (fast) {
        for (unsigned int i = t; i < n; i += 1024) {
            unsigned int key = g_cand_key[i];
            sck[i] = ((unsigned long long)key << 32)
                   | (unsigned long long)(~g_cand_idx[i]);
            atomicAdd(&hist[key >> 21], 1u);
        }
    } else {
        int n4 = N >> 2;
        const uint4* k4 = (const uint4*)g_keys;
        for (int i = t; i < n4; i += 1024) {
            uint4 k = k4[i];
            atomicAdd(&hist[k.x >> 21], 1u);
            atomicAdd(&hist[k.y >> 21], 1u);
            atomicAdd(&hist[k.z >> 21], 1u);
            atomicAdd(&hist[k.w >> 21], 1u);
        }
        for (int i = (n4 << 2) + t; i < N; i += 1024)
            atomicAdd(&hist[g_keys[i] >> 21], 1u);
    }
    __syncthreads();

    // ---- phase 2: block scan over 2048 descending bins (2 bins/thread) ----
    {
        int base = 2047 - t * 2;
        unsigned int c0 = hist[base];
        unsigned int c1 = hist[base - 1];
        unsigned int s = c0 + c1;
        unsigned int incl = s;
#pragma unroll
        for (int off = 1; off < 32; off <<= 1) {
            unsigned int v = __shfl_up_sync(0xFFFFFFFFu, incl, off);
            if (lane >= off) incl += v;
        }
        if (lane == 31) wsum2[w] = incl;
        __syncthreads();
        if (t < 32) {
            unsigned int v = wsum2[t];
#pragma unroll
            for (int off = 1; off < 32; off <<= 1) {
                unsigned int u = __shfl_up_sync(0xFFFFFFFFu, v, off);
                if (t >= off) v += u;
            }
            wsum2[t] = v;
        }
        __syncthreads();
        unsigned int before = incl - s + (w > 0 ? wsum2[w - 1] : 0u);
        unsigned int need = (unsigned int)K;
        if (before < need && before + s >= need)
            s_sel = (before + c0 >= need) ? (unsigned int)base
                                          : (unsigned int)(base - 1);
        __syncthreads();
    }
    unsigned int sel = s_sel;

    // ---- fallback only: collect candidates from g_keys into sck ----
    if (!fast) {
        for (int i = t; i < N; i += 1024) {
            unsigned int key = g_keys[i];
            if ((key >> 21) >= sel) {
                unsigned int p = atomicAdd(&fcnt, 1u);
                if (p < SCK_CAP)
                    sck[p] = ((unsigned long long)key << 32)
                           | (unsigned long long)(~(unsigned int)i);
            }
        }
        __syncthreads();
        n = fcnt < SCK_CAP ? fcnt : SCK_CAP;
    }

    // ---- qinv = 1/|q| ----
    {
        float acc = 0.f;
        for (int i = t; i < D; i += 1024) { float v = q[i]; acc += v * v; }
#pragma unroll
        for (int off = 16; off; off >>= 1)
            acc += __shfl_down_sync(0xFFFFFFFFu, acc, off);
        if (lane == 0) qs[w] = acc;
        __syncthreads();
        if (t == 0) {
            float s = 0.f;
#pragma unroll
            for (int i = 0; i < 32; i++) s += qs[i];
            qinv = 1.0f / fmaxf(sqrtf(s), 1e-8f);
        }
        __syncthreads();   // also: all hist reads done -> safe to reuse
    }

    // ---- phase 3: compact candidates with bin >= sel (reuse hist as u64) --
    unsigned long long* lst = (unsigned long long*)hist;  // 1024 u64 = 8KB
    for (unsigned int i = t; i < n; i += 1024) {
        unsigned long long v = sck[i];
        if (((unsigned int)(v >> 32) >> 21) >= sel) {
            unsigned int p = atomicAdd(&scnt, 1u);
            if (p < LST_CAP) lst[p] = v;
        }
    }
    __syncthreads();
    unsigned int m = scnt;

    // ---- phase 4: exact rank + write ----
    if (m <= LST_CAP) {
        for (unsigned int c = t; c < m; c += 1024) {
            unsigned long long me = lst[c];
            unsigned int rank = 0;
            for (unsigned int j = 0; j < m; j++)
                if (lst[j] > me) rank++;
            if (rank < (unsigned int)K) {
                out[rank]     = key2f((unsigned int)(me >> 32)) * qinv;
                out[K + rank] = (float)(~(unsigned int)me);
            }
        }
    } else {
        // degenerate tie-heavy data: rank directly over staged candidates
        for (unsigned int c = t; c < n; c += 1024) {
            unsigned long long me = sck[c];
            if (((unsigned int)(me >> 32) >> 21) < sel) continue;
            unsigned int rank = 0;
            for (unsigned int j = 0; j < n; j++)
                if (sck[j] > me) rank++;
            if (rank < (unsigned int)K) {
                out[rank]     = key2f((unsigned int)(me >> 32)) * qinv;
                out[K + rank] = (float)(~(unsigned int)me);
            }
        }
    }
    __syncthreads();
    if (t == 0) g_ncand = 0;   // self-clean for next graph replay
}

// ---------------------------------------------------------------------------
extern "C" void kernel_launch(void* const* d_in, const int* in_sizes, int n_in,
                              void* d_out, int out_size) {
    const float* q  = (const float*)d_in[0];
    const float* db = (const float*)d_in[1];
    int N = in_sizes[1] / D;
    int K = out_size / 2;   // values + indices
    float* out = (float*)d_out;

    int simsBlocks = (N + 15) / 16;        // 8 warps, 2 rows/warp

    sims_kernel<<<simsBlocks, 256>>>(db, q, N);
    select_kernel<<<1, 1024>>>(q, out, N, K);
}

// round 11
// speedup vs baseline: 3.1904x; 3.1904x over previous
#include <cuda_runtime.h>
#include <cuda_bf16.h>
#include <math.h>

// ---------------------------------------------------------------------------
// SearchNet: cosine similarity top-k
//   query [512] f32, database [N,512] f32 (N=500000), top_num=100
//   out: [values(K) | indices-as-float(K)] where K = out_size/2
//
// Pipeline (2 kernels, no grid barriers):
//   sims   : keys = dot(q_raw,d)/|d|  (= cos_sim * |q|, order-preserving).
//            Each warp also reduces |q|^2 from its register-resident query
//            slice; lane 0 appends (key,idx) to a global candidate list when
//            key > f2key(T0 * |q|)  -- threshold in KEY units (bug fixed:
//            R10 compared against f2key(T0) in normalized units and matched
//            all 500k rows). T0=0.11 -> ~3200 candidates for N(0,1/512).
//   select : ONE block, 1024 threads:
//              fast path (K <= ncand <= 4864): stage candidates in smem,
//                2048-bin hist of candidates, block scan -> exact bin
//                threshold, compact survivors (~100-400), exact m^2 rank,
//                write top-K scaled by 1/|q|, reset counter.
//              fallback (arbitrary data): full hist + collect over g_keys
//                inside this block — slow but correct.
// ---------------------------------------------------------------------------

#define D 512
#define MAXN (1 << 20)        // >= 500000
#define CAND_CAP 16384
#define SCK_CAP 4864          // staged candidates (38.9KB of smem as u64)
#define LST_CAP 1024          // compacted above-threshold list (reuses hist)
#define T0 0.11f

__device__ unsigned int g_keys[MAXN];
__device__ unsigned int g_ncand;                    // zero at load; reset by select
__device__ unsigned int g_cand_key[CAND_CAP];
__device__ unsigned int g_cand_idx[CAND_CAP];

// float -> order-preserving uint
__device__ __forceinline__ unsigned int f2key(float f) {
    unsigned int u = __float_as_uint(f);
    return (u & 0x80000000u) ? ~u : (u | 0x80000000u);
}
__device__ __forceinline__ float key2f(unsigned int k) {
    unsigned int u = (k & 0x80000000u) ? (k ^ 0x80000000u) : ~k;
    return __uint_as_float(u);
}

// ---------------- sims: dot(q,d)/|d|, 2 rows per warp + candidate append ---
__global__ __launch_bounds__(256) void sims_kernel(const float* __restrict__ db,
                                                   const float* __restrict__ q,
                                                   int N) {
    int warp = (blockIdx.x * blockDim.x + threadIdx.x) >> 5;
    int lane = threadIdx.x & 31;
    int r0 = warp * 2;
    if (r0 >= N) return;
    bool has1 = (r0 + 1) < N;

    const float4* q4 = (const float4*)q;
    float4 q0 = __ldg(&q4[lane]);
    float4 q1 = __ldg(&q4[lane + 32]);
    float4 q2 = __ldg(&q4[lane + 64]);
    float4 q3 = __ldg(&q4[lane + 96]);

    const float4* rowA = (const float4*)(db + (size_t)r0 * D);
    const float4* rowB = (const float4*)(db + (size_t)(r0 + (has1 ? 1 : 0)) * D);

    // front-batch 8 independent streaming DRAM loads (touch-once data)
    float4 a0 = __ldcs(&rowA[lane]);
    float4 a1 = __ldcs(&rowA[lane + 32]);
    float4 a2 = __ldcs(&rowA[lane + 64]);
    float4 a3 = __ldcs(&rowA[lane + 96]);
    float4 b0 = __ldcs(&rowB[lane]);
    float4 b1 = __ldcs(&rowB[lane + 32]);
    float4 b2 = __ldcs(&rowB[lane + 64]);
    float4 b3 = __ldcs(&rowB[lane + 96]);

    float dotA = a0.x*q0.x + a0.y*q0.y + a0.z*q0.z + a0.w*q0.w
               + a1.x*q1.x + a1.y*q1.y + a1.z*q1.z + a1.w*q1.w
               + a2.x*q2.x + a2.y*q2.y + a2.z*q2.z + a2.w*q2.w
               + a3.x*q3.x + a3.y*q3.y + a3.z*q3.z + a3.w*q3.w;
    float n2A  = a0.x*a0.x + a0.y*a0.y + a0.z*a0.z + a0.w*a0.w
               + a1.x*a1.x + a1.y*a1.y + a1.z*a1.z + a1.w*a1.w
               + a2.x*a2.x + a2.y*a2.y + a2.z*a2.z + a2.w*a2.w
               + a3.x*a3.x + a3.y*a3.y + a3.z*a3.z + a3.w*a3.w;
    float dotB = b0.x*q0.x + b0.y*q0.y + b0.z*q0.z + b0.w*q0.w
               + b1.x*q1.x + b1.y*q1.y + b1.z*q1.z + b1.w*q1.w
               + b2.x*q2.x + b2.y*q2.y + b2.z*q2.z + b2.w*q2.w
               + b3.x*q3.x + b3.y*q3.y + b3.z*q3.z + b3.w*q3.w;
    float n2B  = b0.x*b0.x + b0.y*b0.y + b0.z*b0.z + b0.w*b0.w
               + b1.x*b1.x + b1.y*b1.y + b1.z*b1.z + b1.w*b1.w
               + b2.x*b2.x + b2.y*b2.y + b2.z*b2.z + b2.w*b2.w
               + b3.x*b3.x + b3.y*b3.y + b3.z*b3.z + b3.w*b3.w;
    float n2Q  = q0.x*q0.x + q0.y*q0.y + q0.z*q0.z + q0.w*q0.w
               + q1.x*q1.x + q1.y*q1.y + q1.z*q1.z + q1.w*q1.w
               + q2.x*q2.x + q2.y*q2.y + q2.z*q2.z + q2.w*q2.w
               + q3.x*q3.x + q3.y*q3.y + q3.z*q3.z + q3.w*q3.w;

#pragma unroll
    for (int off = 16; off; off >>= 1) {
        dotA += __shfl_down_sync(0xFFFFFFFFu, dotA, off);
        n2A  += __shfl_down_sync(0xFFFFFFFFu, n2A, off);
        dotB += __shfl_down_sync(0xFFFFFFFFu, dotB, off);
        n2B  += __shfl_down_sync(0xFFFFFFFFu, n2B, off);
        n2Q  += __shfl_down_sync(0xFFFFFFFFu, n2Q, off);
    }
    if (lane == 0) {
        // threshold in key units: keys are cos_sim * |q|
        unsigned int t0key = f2key(T0 * sqrtf(n2Q));
        unsigned int kA = f2key(dotA / fmaxf(sqrtf(n2A), 1e-8f));
        g_keys[r0] = kA;
        if (kA > t0key) {
            unsigned int p = atomicAdd(&g_ncand, 1u);
            if (p < CAND_CAP) { g_cand_key[p] = kA; g_cand_idx[p] = (unsigned int)r0; }
        }
        if (has1) {
            unsigned int kB = f2key(dotB / fmaxf(sqrtf(n2B), 1e-8f));
            g_keys[r0 + 1] = kB;
            if (kB > t0key) {
                unsigned int p = atomicAdd(&g_ncand, 1u);
                if (p < CAND_CAP) { g_cand_key[p] = kB; g_cand_idx[p] = (unsigned int)(r0 + 1); }
            }
        }
    }
}

// ---------------- select: single block, hist-of-candidates + exact rank ----
__global__ __launch_bounds__(1024) void select_kernel(
        const float* __restrict__ q, float* __restrict__ out, int N, int K) {
    __shared__ unsigned long long sck[SCK_CAP];  // 38.9KB staged candidates
    __shared__ unsigned int hist[2048];          // 8KB; reused as u64 list later
    __shared__ unsigned int wsum2[32];
    __shared__ unsigned int s_sel, scnt, fcnt;
    __shared__ float qs[32];
    __shared__ float qinv;

    int t = threadIdx.x;
    int lane = t & 31;
    int w = t >> 5;

    unsigned int n = g_ncand;                    // raw append count
    bool fast = (n >= (unsigned int)K && n <= SCK_CAP);

    for (int i = t; i < 2048; i += 1024) hist[i] = 0;
    if (t == 0) { scnt = 0; fcnt = 0; }
    __syncthreads();

    // ---- phase 1: histogram (candidates only, or full keys on fallback) ---
    if (fast) {
        for (unsigned int i = t; i < n; i += 1024) {
            unsigned int key = g_cand_key[i];
            sck[i] = ((unsigned long long)key << 32)
                   | (unsigned long long)(~g_cand_idx[i]);
            atomicAdd(&hist[key >> 21], 1u);
        }
    } else {
        int n4 = N >> 2;
        const uint4* k4 = (const uint4*)g_keys;
        for (int i = t; i < n4; i += 1024) {
            uint4 k = k4[i];
            atomicAdd(&hist[k.x >> 21], 1u);
            atomicAdd(&hist[k.y >> 21], 1u);
            atomicAdd(&hist[k.z >> 21], 1u);
            atomicAdd(&hist[k.w >> 21], 1u);
        }
        for (int i = (n4 << 2) + t; i < N; i += 1024)
            atomicAdd(&hist[g_keys[i] >> 21], 1u);
    }
    __syncthreads();

    // ---- phase 2: block scan over 2048 descending bins (2 bins/thread) ----
    {
        int base = 2047 - t * 2;
        unsigned int c0 = hist[base];
        unsigned int c1 = hist[base - 1];
        unsigned int s = c0 + c1;
        unsigned int incl = s;
#pragma unroll
        for (int off = 1; off < 32; off <<= 1) {
            unsigned int v = __shfl_up_sync(0xFFFFFFFFu, incl, off);
            if (lane >= off) incl += v;
        }
        if (lane == 31) wsum2[w] = incl;
        __syncthreads();
        if (t < 32) {
            unsigned int v = wsum2[t];
#pragma unroll
            for (int off = 1; off < 32; off <<= 1) {
                unsigned int u = __shfl_up_sync(0xFFFFFFFFu, v, off);
                if (t >= off) v += u;
            }
            wsum2[t] = v;
        }
        __syncthreads();
        unsigned int before = incl - s + (w > 0 ? wsum2[w - 1] : 0u);
        unsigned int need = (unsigned int)K;
        if (before < need && before + s >= need)
            s_sel = (before + c0 >= need) ? (unsigned int)base
                                          : (unsigned int)(base - 1);
        __syncthreads();
    }
    unsigned int sel = s_sel;

    // ---- fallback only: collect candidates from g_keys into sck ----
    if (!fast) {
        for (int i = t; i < N; i += 1024) {
            unsigned int key = g_keys[i];
            if ((key >> 21) >= sel) {
                unsigned int p = atomicAdd(&fcnt, 1u);
                if (p < SCK_CAP)
                    sck[p] = ((unsigned long long)key << 32)
                           | (unsigned long long)(~(unsigned int)i);
            }
        }
        __syncthreads();
        n = fcnt < SCK_CAP ? fcnt : SCK_CAP;
    }

    // ---- qinv = 1/|q| ----
    {
        float acc = 0.f;
        for (int i = t; i < D; i += 1024) { float v = q[i]; acc += v * v; }
#pragma unroll
        for (int off = 16; off; off >>= 1)
            acc += __shfl_down_sync(0xFFFFFFFFu, acc, off);
        if (lane == 0) qs[w] = acc;
        __syncthreads();
        if (t == 0) {
            float s = 0.f;
#pragma unroll
            for (int i = 0; i < 32; i++) s += qs[i];
            qinv = 1.0f / fmaxf(sqrtf(s), 1e-8f);
        }
        __syncthreads();   // also: all hist reads done -> safe to reuse
    }

    // ---- phase 3: compact candidates with bin >= sel (reuse hist as u64) --
    unsigned long long* lst = (unsigned long long*)hist;  // 1024 u64 = 8KB
    for (unsigned int i = t; i < n; i += 1024) {
        unsigned long long v = sck[i];
        if (((unsigned int)(v >> 32) >> 21) >= sel) {
            unsigned int p = atomicAdd(&scnt, 1u);
            if (p < LST_CAP) lst[p] = v;
        }
    }
    __syncthreads();
    unsigned int m = scnt;

    // ---- phase 4: exact rank + write ----
    if (m <= LST_CAP) {
        for (unsigned int c = t; c < m; c += 1024) {
            unsigned long long me = lst[c];
            unsigned int rank = 0;
            for (unsigned int j = 0; j < m; j++)
                if (lst[j] > me) rank++;
            if (rank < (unsigned int)K) {
                out[rank]     = key2f((unsigned int)(me >> 32)) * qinv;
                out[K + rank] = (float)(~(unsigned int)me);
            }
        }
    } else {
        // tie-heavy data: rank directly over staged candidates
        for (unsigned int c = t; c < n; c += 1024) {
            unsigned long long me = sck[c];
            if (((unsigned int)(me >> 32) >> 21) < sel) continue;
            unsigned int rank = 0;
            for (unsigned int j = 0; j < n; j++)
                if (sck[j] > me) rank++;
            if (rank < (unsigned int)K) {
                out[rank]     = key2f((unsigned int)(me >> 32)) * qinv;
                out[K + rank] = (float)(~(unsigned int)me);
            }
        }
    }
    __syncthreads();
    if (t == 0) g_ncand = 0;   // self-clean for next graph replay
}

// ---------------------------------------------------------------------------
extern "C" void kernel_launch(void* const* d_in, const int* in_sizes, int n_in,
                              void* d_out, int out_size) {
    const float* q  = (const float*)d_in[0];
    const float* db = (const float*)d_in[1];
    int N = in_sizes[1] / D;
    int K = out_size / 2;   // values + indices
    float* out = (float*)d_out;

    int simsBlocks = (N + 15) / 16;        // 8 warps, 2 rows/warp

    sims_kernel<<<simsBlocks, 256>>>(db, q, N);
    select_kernel<<<1, 1024>>>(q, out, N, K);
}